// round 1
// baseline (speedup 1.0000x reference)
#include <cuda_runtime.h>
#include <math_constants.h>

// Problem constants
#define Bv 4
#define Sv 2048
#define Dv 1024
#define Hv 16
#define HDv 64
#define N3v 3072
#define Mv (Bv*Sv)   // 8192

// ---------------- scratch (device globals; no runtime allocation) -------------
__device__ __align__(256) float g_q[Bv*Hv*Sv*HDv];   // (b,h,s,hd), pre-scaled
__device__ __align__(256) float g_k[Bv*Hv*Sv*HDv];
__device__ __align__(256) float g_v[Bv*Hv*Sv*HDv];
__device__ __align__(256) float g_ctx[Mv*Dv];        // attention output (b,s,d)

// =============================================================================
// Kernel 1: QKV projection  C = X(8192x1024) @ W(1024x3072) + b
// 128x128 tile, BK=8, 256 threads, 8x8 register microtile.
// Epilogue scatters into g_q/g_k/g_v with (b,h,s,hd) layout; q gets *0.125.
// =============================================================================
__global__ __launch_bounds__(256) void gemm_qkv_kernel(
    const float* __restrict__ X,
    const float* __restrict__ W,
    const float* __restrict__ bias)
{
    __shared__ float As[8][128];
    __shared__ float Bs[8][128];

    const int t  = threadIdx.x;
    const int bx = blockIdx.x;   // N tile (24)
    const int by = blockIdx.y;   // M tile (64)
    const int tx = t & 15, ty = t >> 4;
    const int row0 = by * 128;
    const int col0 = bx * 128;

    const int aRow = t >> 1;           // 0..127
    const int aCol = (t & 1) * 4;      // 0 or 4
    const int bRow = t >> 5;           // 0..7
    const int bCol = (t & 31) * 4;     // 0..124

    float acc[8][8];
    #pragma unroll
    for (int i = 0; i < 8; i++)
        #pragma unroll
        for (int j = 0; j < 8; j++) acc[i][j] = 0.f;

    for (int k0 = 0; k0 < Dv; k0 += 8) {
        float4 a = *reinterpret_cast<const float4*>(&X[(row0 + aRow) * Dv + k0 + aCol]);
        As[aCol + 0][aRow] = a.x;
        As[aCol + 1][aRow] = a.y;
        As[aCol + 2][aRow] = a.z;
        As[aCol + 3][aRow] = a.w;
        float4 bv = *reinterpret_cast<const float4*>(&W[(k0 + bRow) * N3v + col0 + bCol]);
        *reinterpret_cast<float4*>(&Bs[bRow][bCol]) = bv;
        __syncthreads();
        #pragma unroll
        for (int kk = 0; kk < 8; kk++) {
            float ar[8], br[8];
            *(float4*)&ar[0] = *(float4*)&As[kk][ty * 8];
            *(float4*)&ar[4] = *(float4*)&As[kk][ty * 8 + 4];
            *(float4*)&br[0] = *(float4*)&Bs[kk][tx * 8];
            *(float4*)&br[4] = *(float4*)&Bs[kk][tx * 8 + 4];
            #pragma unroll
            for (int i = 0; i < 8; i++)
                #pragma unroll
                for (int j = 0; j < 8; j++)
                    acc[i][j] += ar[i] * br[j];
        }
        __syncthreads();
    }

    // Epilogue: scatter into q/k/v
    #pragma unroll
    for (int i = 0; i < 8; i++) {
        const int m = row0 + ty * 8 + i;
        const int bb = m >> 11;          // /2048
        const int s  = m & 2047;
        #pragma unroll
        for (int j = 0; j < 8; j++) {
            const int n = col0 + tx * 8 + j;
            float v = acc[i][j] + bias[n];
            const int sel = n >> 10;     // 0=q 1=k 2=v
            const int d   = n & 1023;
            const int h   = d >> 6;
            const int hd  = d & 63;
            const int idx = ((bb * Hv + h) * Sv + s) * HDv + hd;
            if (sel == 0)      g_q[idx] = v * 0.125f;
            else if (sel == 1) g_k[idx] = v;
            else               g_v[idx] = v;
        }
    }
}

// =============================================================================
// Kernel 2: fp32 flash attention. One block = (b, h, 64 q-rows).
// 256 threads; microtile 4x4 with interleaved mapping row=ty+16i, col=tx+16j.
// smem tiles pitch 65 (conflict-free), online softmax, masked keys -> -1e30.
// =============================================================================
#define PT 65
#define ATTN_SMEM_BYTES ((4 * 64 * PT + 64 * 3 + 256) * 4 + 64 * 4)

__global__ __launch_bounds__(256) void attn_kernel(const int* __restrict__ mask)
{
    extern __shared__ float sm[];
    float* sQ   = sm;                 // [hd][r]  pitch PT
    float* sK   = sQ + 64 * PT;       // [hd][c]  pitch PT
    float* sV   = sK + 64 * PT;       // [c][hd]  pitch PT
    float* sS   = sV + 64 * PT;       // [r][c]   pitch PT
    float* m_s    = sS + 64 * PT;     // 64
    float* l_s    = m_s + 64;         // 64
    float* corr_s = l_s + 64;         // 64
    float* red    = corr_s + 64;      // 256
    int*   smask  = (int*)(red + 256);// 64

    const int t  = threadIdx.x;
    const int qt = blockIdx.x;
    const int h  = blockIdx.y;
    const int b  = blockIdx.z;
    const int tx = t & 15, ty = t >> 4;

    const int rr = t >> 2;            // 0..63 (row for tile loads)
    const int qd = (t & 3) * 16;      // hd chunk start

    // ---- load Q tile transposed: sQ[hd][r] ----
    const float* qptr = g_q + ((b * Hv + h) * Sv + qt * 64) * HDv;
    #pragma unroll
    for (int u = 0; u < 4; u++) {
        float4 v = *(const float4*)&qptr[rr * 64 + qd + u * 4];
        sQ[(qd + u * 4 + 0) * PT + rr] = v.x;
        sQ[(qd + u * 4 + 1) * PT + rr] = v.y;
        sQ[(qd + u * 4 + 2) * PT + rr] = v.z;
        sQ[(qd + u * 4 + 3) * PT + rr] = v.w;
    }
    if (t < 64) { m_s[t] = -1e30f; l_s[t] = 0.f; }

    float o[4][4];
    #pragma unroll
    for (int i = 0; i < 4; i++)
        #pragma unroll
        for (int j = 0; j < 4; j++) o[i][j] = 0.f;

    const int r = t & 63;
    const int p = t >> 6;

    for (int kt = 0; kt < Sv / 64; kt++) {
        __syncthreads();   // protect prior-iteration smem reads

        // ---- load K (transposed) and V tiles ----
        const float* kptr = g_k + ((b * Hv + h) * Sv + kt * 64) * HDv;
        const float* vptr = g_v + ((b * Hv + h) * Sv + kt * 64) * HDv;
        #pragma unroll
        for (int u = 0; u < 4; u++) {
            float4 v = *(const float4*)&kptr[rr * 64 + qd + u * 4];
            sK[(qd + u * 4 + 0) * PT + rr] = v.x;
            sK[(qd + u * 4 + 1) * PT + rr] = v.y;
            sK[(qd + u * 4 + 2) * PT + rr] = v.z;
            sK[(qd + u * 4 + 3) * PT + rr] = v.w;
        }
        #pragma unroll
        for (int u = 0; u < 4; u++) {
            float4 v = *(const float4*)&vptr[rr * 64 + qd + u * 4];
            sV[rr * PT + qd + u * 4 + 0] = v.x;
            sV[rr * PT + qd + u * 4 + 1] = v.y;
            sV[rr * PT + qd + u * 4 + 2] = v.z;
            sV[rr * PT + qd + u * 4 + 3] = v.w;
        }
        if (t < 64) smask[t] = mask[b * Sv + kt * 64 + t];
        __syncthreads();

        // ---- scores: S = Q K^T (q pre-scaled) ----
        float sc[4][4];
        #pragma unroll
        for (int i = 0; i < 4; i++)
            #pragma unroll
            for (int j = 0; j < 4; j++) sc[i][j] = 0.f;
        #pragma unroll 4
        for (int k = 0; k < 64; k++) {
            float a[4], bb2[4];
            #pragma unroll
            for (int i = 0; i < 4; i++) a[i]   = sQ[k * PT + ty + 16 * i];
            #pragma unroll
            for (int j = 0; j < 4; j++) bb2[j] = sK[k * PT + tx + 16 * j];
            #pragma unroll
            for (int i = 0; i < 4; i++)
                #pragma unroll
                for (int j = 0; j < 4; j++)
                    sc[i][j] += a[i] * bb2[j];
        }
        #pragma unroll
        for (int i = 0; i < 4; i++)
            #pragma unroll
            for (int j = 0; j < 4; j++) {
                const int c = tx + 16 * j;
                sS[(ty + 16 * i) * PT + c] = smask[c] ? sc[i][j] : -1e30f;
            }
        __syncthreads();

        // ---- row max (4 partials per row) ----
        {
            float mx = -1e30f;
            const int c0 = p * 16;
            #pragma unroll
            for (int c = 0; c < 16; c++) mx = fmaxf(mx, sS[r * PT + c0 + c]);
            red[p * 64 + r] = mx;
        }
        __syncthreads();
        if (t < 64) {
            float mt = fmaxf(fmaxf(red[t], red[64 + t]), fmaxf(red[128 + t], red[192 + t]));
            float m_old = m_s[t];
            float m_new = fmaxf(m_old, mt);
            float corr  = __expf(m_old - m_new);
            m_s[t] = m_new; corr_s[t] = corr; l_s[t] *= corr;
        }
        __syncthreads();

        // ---- exponentiate + partial row sums ----
        {
            const float mrow = m_s[r];
            float lsum = 0.f;
            const int c0 = p * 16;
            #pragma unroll
            for (int c = 0; c < 16; c++) {
                float e = __expf(sS[r * PT + c0 + c] - mrow);
                sS[r * PT + c0 + c] = e;
                lsum += e;
            }
            red[p * 64 + r] = lsum;
        }
        __syncthreads();
        if (t < 64) l_s[t] += red[t] + red[64 + t] + red[128 + t] + red[192 + t];

        // ---- rescale accumulators, then O += P V ----
        #pragma unroll
        for (int i = 0; i < 4; i++) {
            const float cf = corr_s[ty + 16 * i];
            #pragma unroll
            for (int j = 0; j < 4; j++) o[i][j] *= cf;
        }
        #pragma unroll 4
        for (int c = 0; c < 64; c++) {
            float a[4], bb2[4];
            #pragma unroll
            for (int i = 0; i < 4; i++) a[i]   = sS[(ty + 16 * i) * PT + c];
            #pragma unroll
            for (int j = 0; j < 4; j++) bb2[j] = sV[c * PT + tx + 16 * j];
            #pragma unroll
            for (int i = 0; i < 4; i++)
                #pragma unroll
                for (int j = 0; j < 4; j++)
                    o[i][j] += a[i] * bb2[j];
        }
    }
    __syncthreads();

    // ---- normalize and write to (b,s,d) context ----
    float* optr = g_ctx + (size_t)(b * Sv + qt * 64) * Dv + h * HDv;
    #pragma unroll
    for (int i = 0; i < 4; i++) {
        const int rl = ty + 16 * i;
        const float inv = 1.0f / l_s[rl];
        #pragma unroll
        for (int j = 0; j < 4; j++)
            optr[rl * Dv + tx + 16 * j] = o[i][j] * inv;
    }
}

// =============================================================================
// Kernel 3: output projection  out = ctx(8192x1024) @ Wo(1024x1024) + b_out
// =============================================================================
__global__ __launch_bounds__(256) void gemm_out_kernel(
    const float* __restrict__ W,
    const float* __restrict__ bias,
    float* __restrict__ out)
{
    __shared__ float As[8][128];
    __shared__ float Bs[8][128];

    const int t  = threadIdx.x;
    const int bx = blockIdx.x;   // N tile (8)
    const int by = blockIdx.y;   // M tile (64)
    const int tx = t & 15, ty = t >> 4;
    const int row0 = by * 128;
    const int col0 = bx * 128;

    const int aRow = t >> 1;
    const int aCol = (t & 1) * 4;
    const int bRow = t >> 5;
    const int bCol = (t & 31) * 4;

    float acc[8][8];
    #pragma unroll
    for (int i = 0; i < 8; i++)
        #pragma unroll
        for (int j = 0; j < 8; j++) acc[i][j] = 0.f;

    for (int k0 = 0; k0 < Dv; k0 += 8) {
        float4 a = *reinterpret_cast<const float4*>(&g_ctx[(size_t)(row0 + aRow) * Dv + k0 + aCol]);
        As[aCol + 0][aRow] = a.x;
        As[aCol + 1][aRow] = a.y;
        As[aCol + 2][aRow] = a.z;
        As[aCol + 3][aRow] = a.w;
        float4 bv = *reinterpret_cast<const float4*>(&W[(k0 + bRow) * Dv + col0 + bCol]);
        *reinterpret_cast<float4*>(&Bs[bRow][bCol]) = bv;
        __syncthreads();
        #pragma unroll
        for (int kk = 0; kk < 8; kk++) {
            float ar[8], br[8];
            *(float4*)&ar[0] = *(float4*)&As[kk][ty * 8];
            *(float4*)&ar[4] = *(float4*)&As[kk][ty * 8 + 4];
            *(float4*)&br[0] = *(float4*)&Bs[kk][tx * 8];
            *(float4*)&br[4] = *(float4*)&Bs[kk][tx * 8 + 4];
            #pragma unroll
            for (int i = 0; i < 8; i++)
                #pragma unroll
                for (int j = 0; j < 8; j++)
                    acc[i][j] += ar[i] * br[j];
        }
        __syncthreads();
    }

    #pragma unroll
    for (int i = 0; i < 8; i++) {
        const int m = row0 + ty * 8 + i;
        #pragma unroll
        for (int jj = 0; jj < 2; jj++) {
            const int n = col0 + tx * 8 + jj * 4;
            float4 v;
            v.x = acc[i][jj * 4 + 0] + bias[n + 0];
            v.y = acc[i][jj * 4 + 1] + bias[n + 1];
            v.z = acc[i][jj * 4 + 2] + bias[n + 2];
            v.w = acc[i][jj * 4 + 3] + bias[n + 3];
            *reinterpret_cast<float4*>(&out[(size_t)m * Dv + n]) = v;
        }
    }
}

// =============================================================================
extern "C" void kernel_launch(void* const* d_in, const int* in_sizes, int n_in,
                              void* d_out, int out_size)
{
    const float* x     = (const float*)d_in[0];
    const float* w_in  = (const float*)d_in[1];
    const float* b_in  = (const float*)d_in[2];
    const float* w_out = (const float*)d_in[3];
    const float* b_out = (const float*)d_in[4];
    const int*   mask  = (const int*)d_in[5];
    float* out = (float*)d_out;

    cudaFuncSetAttribute(attn_kernel, cudaFuncAttributeMaxDynamicSharedMemorySize,
                         ATTN_SMEM_BYTES);

    gemm_qkv_kernel<<<dim3(N3v / 128, Mv / 128), 256>>>(x, w_in, b_in);
    attn_kernel<<<dim3(Sv / 64, Hv, Bv), 256, ATTN_SMEM_BYTES>>>(mask);
    gemm_out_kernel<<<dim3(Dv / 128, Mv / 128), 256>>>(w_out, b_out, out);
}